// round 14
// baseline (speedup 1.0000x reference)
#include <cuda_runtime.h>
#include <cuda_fp16.h>
#include <math_constants.h>

// warpLayer, round 14: single fused kernel. Blocks 0..NB-1 build the fp16
// channel-major corner table (R10's coalesced chunk indexing), signal via a
// device counter; all blocks overlap their table-free prologue with the
// build, spin-wait, then run the R9 gather loop. Counters self-reset.

#define NPIX  (16 * 512 * 512)
#define NCELL (255 * 255)
#define NB    256                     // builder blocks (<= wave-1 residency)

__device__ uint4 g_tab[NCELL * 4];    // 4.16 MB
__device__ int      g_done = 0;       // builder blocks arrived
__device__ unsigned g_fin  = 0;       // finished blocks (for reset)

// C = wrap(atan2(y, x)) * 255/(2*pi) in [0, 255]
__device__ __forceinline__ float angle_c(float y, float x)
{
    const float K = 255.0f / (2.0f * CUDART_PI_F);
    float ax = fabsf(x), ay = fabsf(y);
    float mx = fmaxf(ax, ay), mn = fminf(ax, ay);
    float a  = __fdividef(mn, mx);
    float s  = a * a;
    float p  =            -0.01172120f;
    p = fmaf(p, s,  0.05265332f);
    p = fmaf(p, s, -0.11643287f);
    p = fmaf(p, s,  0.19354346f);
    p = fmaf(p, s, -0.33262347f);
    p = fmaf(p, s,  0.99997726f);
    float r = a * p * K;
    if (ay > ax)  r = 63.75f - r;
    if (x < 0.0f) r = 127.5f - r;
    if (y < 0.0f) r = 255.0f - r;
    return r;
}

// owner: pack (cell:16 | w0q:8 | w1q:8)
__device__ __forceinline__ unsigned prep(const float4& im)
{
    float c0 = fminf(angle_c(im.y, im.x), 254.0f);
    float c1 = fminf(angle_c(im.w, im.z), 254.0f);
    float fi = floorf(c0);
    float fj = floorf(c1);
    int cell = (int)fi * 255 + (int)fj;
    int w0q = min(__float2int_rn((c0 - fi) * 256.0f), 255);
    int w1q = min(__float2int_rn((c1 - fj) * 256.0f), 255);
    return ((unsigned)cell << 16) | ((unsigned)w0q << 8) | (unsigned)w1q;
}

// receiver: unpack w half2, bilinear on one 64B cell chunk, return packed half2
__device__ __forceinline__ unsigned bilin(const uint4& v, unsigned u)
{
    unsigned hb = __byte_perm(u, 0x64646464u, 0x4041);
    __half2 h = __hfma2(*reinterpret_cast<__half2*>(&hb),
                        __float2half2_rn(0.00390625f),      // 1/256
                        __float2half2_rn(-4.0f));           // (w0, w1)
    __half2 om = __hsub2(__float2half2_rn(1.0f), h);
    __half2 p  = __halves2half2(__high2half(om), __high2half(h));
    __half2 A0 = __hmul2(__low2half2(om), p);   // (a00, a01)
    __half2 A1 = __hmul2(__low2half2(h),  p);   // (a10, a11)

    __half2 acc = __hmul2(__low2half2(A0),  *reinterpret_cast<const __half2*>(&v.x));
    acc = __hfma2(__high2half2(A0), *reinterpret_cast<const __half2*>(&v.y), acc);
    acc = __hfma2(__low2half2(A1),  *reinterpret_cast<const __half2*>(&v.z), acc);
    acc = __hfma2(__high2half2(A1), *reinterpret_cast<const __half2*>(&v.w), acc);
    return *reinterpret_cast<unsigned*>(&acc);
}

__global__ __launch_bounds__(256, 6)
void warp_fused(const float4* __restrict__ img, const float* __restrict__ wt,
                float4* __restrict__ out)
{
    const unsigned FULL = 0xffffffffu;
    int tid   = threadIdx.x;
    int lane  = tid & 31;
    int warp  = (blockIdx.x * blockDim.x + tid) >> 5;
    int pbase = warp << 6;                 // 64 pixels per warp

    // ---- phase 0: builder blocks fill the table (coalesced chunk index) ----
    if (blockIdx.x < NB) {
        for (int idx = blockIdx.x * 256 + tid; idx < NCELL * 4; idx += NB * 256) {
            int cell = idx >> 2, k = idx & 3;
            int cp = (k == 1) ? 2 : (k == 2) ? 1 : k;   // perm {0,2,1,3}
            int i = cell / 255;
            int j = cell - i * 255;
            const float* base = wt + ((i << 8) + j) * 8 + (cp << 1);
            float2 c00 = *(const float2*)(base);
            float2 c01 = *(const float2*)(base + 8);
            float2 c10 = *(const float2*)(base + 256 * 8);
            float2 c11 = *(const float2*)(base + 256 * 8 + 8);
            const float S = 0.0005f;
            __half2 h00 = __floats2half2_rn(S * c00.x, S * c00.y);
            __half2 h01 = __floats2half2_rn(S * c01.x, S * c01.y);
            __half2 h10 = __floats2half2_rn(S * c10.x, S * c10.y);
            __half2 h11 = __floats2half2_rn(S * c11.x, S * c11.y);
            uint4 o;
            o.x = *reinterpret_cast<unsigned*>(&h00);
            o.y = *reinterpret_cast<unsigned*>(&h01);
            o.z = *reinterpret_cast<unsigned*>(&h10);
            o.w = *reinterpret_cast<unsigned*>(&h11);
            g_tab[idx] = o;
        }
        __syncthreads();
        if (tid == 0) {
            __threadfence();                 // table visible before arrive
            atomicAdd(&g_done, 1);
        }
    }

    // ---- phase 1: table-independent prologue (overlaps the build) ----
    float4 imA = img[pbase + lane];
    float4 imB = img[pbase + 32 + lane];
    unsigned uA = prep(imA);
    unsigned uB = prep(imB);

    // ---- phase 2: wait for table ----
    if (tid == 0) {
        while (*(volatile int*)&g_done < NB) __nanosleep(64);
        __threadfence();                     // acquire before table reads
    }
    __syncthreads();

    // ---- phase 3: gather loop (R9 body, L1 stays warm) ----
    int k = lane & 3;
    int g = lane >> 2;

    #pragma unroll
    for (int r = 0; r < 4; r++) {
        int q = r * 8 + g;

        unsigned bA = __shfl_sync(FULL, uA, q);
        unsigned bB = __shfl_sync(FULL, uB, q);

        uint4 vA = __ldg(&g_tab[((bA >> 16) << 2) + k]);
        uint4 vB = __ldg(&g_tab[((bB >> 16) << 2) + k]);

        int PA = pbase + q;
        int PB = pbase + 32 + q;
        float4 reA, reB;
        if (k == 2) { reA = __ldg(&img[PA]); reB = __ldg(&img[PB]); }

        unsigned accA = bilin(vA, bA);
        unsigned accB = bilin(vB, bB);

        unsigned rxA = __shfl_xor_sync(FULL, accA, 2);
        unsigned rxB = __shfl_xor_sync(FULL, accB, 2);

        float2 oa = __half22float2(*reinterpret_cast<__half2*>(&accA));
        float2 ra = __half22float2(*reinterpret_cast<__half2*>(&rxA));
        float2 ob = __half22float2(*reinterpret_cast<__half2*>(&accB));
        float2 rb = __half22float2(*reinterpret_cast<__half2*>(&rxB));

        float4 svA = (k == 2) ? reA : make_float4(oa.x, oa.y, ra.x, ra.y);
        float4 svB = (k == 2) ? reB : make_float4(ob.x, ob.y, rb.x, rb.y);
        if (k < 3) {
            out[(size_t)PA * 3 + k] = svA;
            out[(size_t)PB * 3 + k] = svB;
        }
    }

    // ---- phase 4: last block resets counters for the next replay ----
    __syncthreads();
    if (tid == 0) {
        unsigned f = atomicAdd(&g_fin, 1u);
        if (f == gridDim.x - 1u) {
            g_done = 0;
            g_fin  = 0u;
        }
    }
}

extern "C" void kernel_launch(void* const* d_in, const int* in_sizes, int n_in,
                              void* d_out, int out_size)
{
    const float4* img = (const float4*)d_in[0];
    const float*  wt  = (const float*)d_in[1];
    float4*       out = (float4*)d_out;

    warp_fused<<<NPIX / 512, 256>>>(img, wt, out);
}

// round 15
// speedup vs baseline: 1.2447x; 1.2447x over previous
#include <cuda_runtime.h>
#include <cuda_fp16.h>
#include <cuda_fp8.h>
#include <math_constants.h>

// warpLayer, round 15: fp8-e4m3 corner table (32B/cell, halves gather L2
// bytes — kernel was at ~92% of the LTS cap). Structure = R10: PDL overlap,
// 2 px/thread, channel-major perm{0,2,1,3}, xor-2 exchange, fp32 scale at store.

#define NPIX  (16 * 512 * 512)
#define NCELL (255 * 255)

__device__ uint2 g_tab8[NCELL * 4];   // 2.08 MB, 8B chunk = 4 corners x 2ch fp8

__global__ __launch_bounds__(256)
void build_tab(const float* __restrict__ wt)
{
    int idx = blockIdx.x * blockDim.x + threadIdx.x;
    if (idx < NCELL * 4) {
        int cell = idx >> 2, k = idx & 3;
        int cp = (k == 1) ? 2 : (k == 2) ? 1 : k;   // perm {0,2,1,3}
        int i = cell / 255;
        int j = cell - i * 255;
        const float* base = wt + ((i << 8) + j) * 8 + (cp << 1);
        float2 c00 = *(const float2*)(base);
        float2 c01 = *(const float2*)(base + 8);
        float2 c10 = *(const float2*)(base + 256 * 8);
        float2 c11 = *(const float2*)(base + 256 * 8 + 8);
        unsigned p00 = __nv_cvt_float2_to_fp8x2(c00, __NV_SATFINITE, __NV_E4M3);
        unsigned p01 = __nv_cvt_float2_to_fp8x2(c01, __NV_SATFINITE, __NV_E4M3);
        unsigned p10 = __nv_cvt_float2_to_fp8x2(c10, __NV_SATFINITE, __NV_E4M3);
        unsigned p11 = __nv_cvt_float2_to_fp8x2(c11, __NV_SATFINITE, __NV_E4M3);
        uint2 o;
        o.x = p00 | (p01 << 16);
        o.y = p10 | (p11 << 16);
        g_tab8[idx] = o;
    }
    cudaTriggerProgrammaticLaunchCompletion();
}

// C = wrap(atan2(y, x)) * 255/(2*pi) in [0, 255]
__device__ __forceinline__ float angle_c(float y, float x)
{
    const float K = 255.0f / (2.0f * CUDART_PI_F);
    float ax = fabsf(x), ay = fabsf(y);
    float mx = fmaxf(ax, ay), mn = fminf(ax, ay);
    float a  = __fdividef(mn, mx);
    float s  = a * a;
    float p  =            -0.01172120f;
    p = fmaf(p, s,  0.05265332f);
    p = fmaf(p, s, -0.11643287f);
    p = fmaf(p, s,  0.19354346f);
    p = fmaf(p, s, -0.33262347f);
    p = fmaf(p, s,  0.99997726f);
    float r = a * p * K;
    if (ay > ax)  r = 63.75f - r;
    if (x < 0.0f) r = 127.5f - r;
    if (y < 0.0f) r = 255.0f - r;
    return r;
}

// owner: pack (cell:16 | w0q:8 | w1q:8)
__device__ __forceinline__ unsigned prep(const float4& im)
{
    float c0 = fminf(angle_c(im.y, im.x), 254.0f);
    float c1 = fminf(angle_c(im.w, im.z), 254.0f);
    float fi = floorf(c0);
    float fj = floorf(c1);
    int cell = (int)fi * 255 + (int)fj;
    int w0q = min(__float2int_rn((c0 - fi) * 256.0f), 255);
    int w1q = min(__float2int_rn((c1 - fj) * 256.0f), 255);
    return ((unsigned)cell << 16) | ((unsigned)w0q << 8) | (unsigned)w1q;
}

__device__ __forceinline__ __half2 fp8x2_h2(unsigned s)
{
    __half2_raw hr = __nv_cvt_fp8x2_to_halfraw2((__nv_fp8x2_storage_t)s, __NV_E4M3);
    return *reinterpret_cast<__half2*>(&hr);
}

// receiver: unpack w, convert fp8 corners, bilinear -> packed half2
__device__ __forceinline__ unsigned bilin(const uint2& v, unsigned u)
{
    unsigned hb = __byte_perm(u, 0x64646464u, 0x4041);
    __half2 h = __hfma2(*reinterpret_cast<__half2*>(&hb),
                        __float2half2_rn(0.00390625f),      // 1/256
                        __float2half2_rn(-4.0f));           // (w0, w1)
    __half2 om = __hsub2(__float2half2_rn(1.0f), h);
    __half2 p  = __halves2half2(__high2half(om), __high2half(h));
    __half2 A0 = __hmul2(__low2half2(om), p);   // (a00, a01)
    __half2 A1 = __hmul2(__low2half2(h),  p);   // (a10, a11)

    __half2 h00 = fp8x2_h2(v.x & 0xffffu);
    __half2 h01 = fp8x2_h2(v.x >> 16);
    __half2 h10 = fp8x2_h2(v.y & 0xffffu);
    __half2 h11 = fp8x2_h2(v.y >> 16);

    __half2 acc = __hmul2(__low2half2(A0),  h00);
    acc = __hfma2(__high2half2(A0), h01, acc);
    acc = __hfma2(__low2half2(A1),  h10, acc);
    acc = __hfma2(__high2half2(A1), h11, acc);
    return *reinterpret_cast<unsigned*>(&acc);
}

__global__ __launch_bounds__(256, 6)
void warp_main(const float4* __restrict__ img, float4* __restrict__ out)
{
    const unsigned FULL = 0xffffffffu;
    const float S = 0.0005f;
    int lane  = threadIdx.x & 31;
    int warp  = (blockIdx.x * blockDim.x + threadIdx.x) >> 5;
    int pbase = warp << 6;                 // 64 pixels per warp

    // ---- table-independent prologue (overlaps build_tab via PDL) ----
    float4 imA = img[pbase + lane];
    float4 imB = img[pbase + 32 + lane];
    unsigned uA = prep(imA);
    unsigned uB = prep(imB);

    cudaGridDependencySynchronize();

    int k = lane & 3;
    int g = lane >> 2;

    #pragma unroll
    for (int r = 0; r < 4; r++) {
        int q = r * 8 + g;

        unsigned bA = __shfl_sync(FULL, uA, q);
        unsigned bB = __shfl_sync(FULL, uB, q);

        uint2 vA = __ldg(&g_tab8[((bA >> 16) << 2) + k]);
        uint2 vB = __ldg(&g_tab8[((bB >> 16) << 2) + k]);

        int PA = pbase + q;
        int PB = pbase + 32 + q;
        float4 reA, reB;
        if (k == 2) { reA = __ldg(&img[PA]); reB = __ldg(&img[PB]); }

        unsigned accA = bilin(vA, bA);
        unsigned accB = bilin(vB, bB);

        unsigned rxA = __shfl_xor_sync(FULL, accA, 2);
        unsigned rxB = __shfl_xor_sync(FULL, accB, 2);

        float2 oa = __half22float2(*reinterpret_cast<__half2*>(&accA));
        float2 ra = __half22float2(*reinterpret_cast<__half2*>(&rxA));
        float2 ob = __half22float2(*reinterpret_cast<__half2*>(&accB));
        float2 rb = __half22float2(*reinterpret_cast<__half2*>(&rxB));

        float4 svA = (k == 2) ? reA
                   : make_float4(oa.x * S, oa.y * S, ra.x * S, ra.y * S);
        float4 svB = (k == 2) ? reB
                   : make_float4(ob.x * S, ob.y * S, rb.x * S, rb.y * S);
        if (k < 3) {
            out[(size_t)PA * 3 + k] = svA;
            out[(size_t)PB * 3 + k] = svB;
        }
    }
}

extern "C" void kernel_launch(void* const* d_in, const int* in_sizes, int n_in,
                              void* d_out, int out_size)
{
    const float4* img = (const float4*)d_in[0];
    const float*  wt  = (const float*)d_in[1];
    float4*       out = (float4*)d_out;

    build_tab<<<(NCELL * 4 + 255) / 256, 256>>>(wt);

    cudaLaunchConfig_t cfg = {};
    cfg.gridDim  = dim3(NPIX / 512, 1, 1);
    cfg.blockDim = dim3(256, 1, 1);
    cfg.dynamicSmemBytes = 0;
    cfg.stream = 0;
    cudaLaunchAttribute attr[1];
    attr[0].id = cudaLaunchAttributeProgrammaticStreamSerialization;
    attr[0].val.programmaticStreamSerializationAllowed = 1;
    cfg.attrs = attr;
    cfg.numAttrs = 1;
    cudaLaunchKernelEx(&cfg, warp_main, img, out);
}